// round 11
// baseline (speedup 1.0000x reference)
#include <cuda_runtime.h>

#define Vdim   96
#define Kdim   20
#define Bdim   256
#define Ddim   1024
#define NIJ    9
#define GROUPS 144      // 3*3*4*2*2
#define VK     1920     // Vdim*Kdim

// mega kernel geometry — R8/R10-proven streaming config + 10 prep blocks
#define BPB    64                  // b's per yphi block
#define SPLITS (Bdim / BPB)        // 4
#define NPHI   (GROUPS * SPLITS)   // 576 yphi-role blocks
#define DCHUNK 20                  // d's per Y block
#define NYB    52                  // ceil(1024/20)
#define NY     (NIJ * NYB)         // 468 Y-role blocks
#define NPREP  10                  // prep-role blocks (first in grid)
#define NBLK   (NPREP + NY + NPHI) // 1054
#define TMEGA  480                 // threads
#define NWARP  (TMEGA / 32)        // 15

// ---- scratch (static device globals — no runtime allocation) ----
__device__ float        g_ytr[NIJ * Ddim];    // sum over (e,n,c,v) of Y -> [ij][d]
__device__ float        g_L1[NIJ * VK];       // _T0 + log wt_i + log wr_j per (ij,v,k)
__device__ float        g_W2[GROUPS * Kdim];  // lq - logZ + L3 per (group,k)
__device__ float        g_Wb[NIJ * Bdim];     // sum over (enc,v,k) of yphi -> [ij][b]
__device__ double       g_loss;
__device__ unsigned int g_prepcnt;            // static zero-init; reset by k_finish

// ---------------------------------------------------------------------------
// MEGA: prep (10 blocks) + Y stream (468) + yphi stream (576) in ONE launch.
// yphi blocks gate on the prep counter; Y blocks stream immediately.
// ---------------------------------------------------------------------------
__global__ __launch_bounds__(TMEGA) void k_mega(
    const float* __restrict__ yphi, const float* __restrict__ Yv,
    const float* __restrict__ T0p,  const float* __restrict__ tp,
    const float* __restrict__ rp,   const float* __restrict__ ep,
    const float* __restrict__ enp,  const float* __restrict__ ecp)
{
    int blk = blockIdx.x, t = threadIdx.x;
    int lane = t & 31, w = t >> 5;

    if (blk < NPREP) {
        // ================= PREP ROLE =================
        if (blk > 0) {
            // ---- L1 slab for ij = blk-1: _T0 + log wt_i + log wr_j ----
            int ij = blk - 1;
            int i = ij / 3, j = ij % 3;
            for (int idx = t; idx < VK; idx += TMEGA) {
                float t0 = T0p[idx];
                float lwt = 0.f, lwr = 0.f;
                if (i < 2) {
                    float s = 1.f / (1.f + __expf(-tp[idx]));
                    lwt = __logf((i == 0) ? s : 1.f - s);
                }
                if (j < 2) {
                    float s = 1.f / (1.f + __expf(-rp[idx]));
                    lwr = __logf((j == 0) ? s : 1.f - s);
                }
                g_L1[ij * VK + idx] = t0 + lwt + lwr;
            }
        } else {
            // ---- block 0: reductions + W2 + zeroing ----
            __shared__ float se[VK], st[VK], sr[VK];
            __shared__ float sprm[8 * Kdim];      // ep(4)|enp(2)|ecp(2)
            __shared__ float scolsum[Kdim];
            __shared__ float sZraw[NIJ * Kdim];
            __shared__ float slz[NIJ * Kdim];
            __shared__ float slpe[4 * Kdim], slpn[2 * Kdim], slpc[2 * Kdim];

            if (t < 8 * Kdim)
                sprm[t] = (t < 4 * Kdim) ? ep[t]
                        : (t < 6 * Kdim) ? enp[t - 4 * Kdim]
                                         : ecp[t - 6 * Kdim];
            for (int i = t; i < VK; i += TMEGA) {
                se[i] = __expf(T0p[i]);
                st[i] = 1.f / (1.f + __expf(-tp[i]));
                sr[i] = 1.f / (1.f + __expf(-rp[i]));
            }
            for (int i = t; i < NIJ * Bdim; i += TMEGA) g_Wb[i] = 0.f;
            if (t == 0) g_loss = 0.0;
            __syncthreads();

            // colsum (warp per column, strided over 15 warps)
            for (int o = w; o < Kdim; o += NWARP) {
                float s = 0.f;
                for (int v = lane; v < Vdim; v += 32) s += se[v * Kdim + o];
#pragma unroll
                for (int off = 16; off; off >>= 1)
                    s += __shfl_down_sync(0xffffffffu, s, off);
                if (lane == 0) scolsum[o] = s;
            }
            // raw Z[ij][k] (warp per output)
            for (int o = w; o < NIJ * Kdim; o += NWARP) {
                int ij = o / Kdim, k = o - ij * Kdim, i = ij / 3, j = ij % 3;
                float s = 0.f;
                for (int v = lane; v < Vdim; v += 32) {
                    int r = v * Kdim + k;
                    float wt = (i == 0) ? st[r] : (i == 1) ? 1.f - st[r] : 1.f;
                    float wr = (j == 0) ? sr[r] : (j == 1) ? 1.f - sr[r] : 1.f;
                    s += se[r] * wt * wr;
                }
#pragma unroll
                for (int off = 16; off; off >>= 1)
                    s += __shfl_down_sync(0xffffffffu, s, off);
                if (lane == 0) sZraw[o] = s;
            }
            __syncthreads();

            if (t < Kdim) {
                float s, l;
                s = 0.f; for (int e = 0; e < 4; ++e) s += __expf(sprm[e * Kdim + t]);
                l = __logf(s);
                for (int e = 0; e < 4; ++e) slpe[e * Kdim + t] = sprm[e * Kdim + t] - l;
                s = 0.f; for (int n = 0; n < 2; ++n) s += __expf(sprm[(4 + n) * Kdim + t]);
                l = __logf(s);
                for (int n = 0; n < 2; ++n) slpn[n * Kdim + t] = sprm[(4 + n) * Kdim + t] - l;
                s = 0.f; for (int c = 0; c < 2; ++c) s += __expf(sprm[(6 + c) * Kdim + t]);
                l = __logf(s);
                for (int c = 0; c < 2; ++c) slpc[c * Kdim + t] = sprm[(6 + c) * Kdim + t] - l;
            }
            if (t < NIJ * Kdim) {
                int ij = t / Kdim, k = t - ij * Kdim;
                int i = ij / 3, j = ij % 3;
                float inv = 1.f / scolsum[k];
                float pt = sZraw[2 * Kdim + k] * inv;   // ij=(0,2)
                float pr = sZraw[6 * Kdim + k] * inv;   // ij=(2,0)
                float lqt = (i == 0) ? __logf(pt) : (i == 1) ? __logf(1.f - pt) : 0.f;
                float lqr = (j == 0) ? __logf(pr) : (j == 1) ? __logf(1.f - pr) : 0.f;
                slz[t] = lqt + lqr - __logf(sZraw[t]);
            }
            __syncthreads();

            for (int idx = t; idx < GROUPS * Kdim; idx += TMEGA) {
                int g = idx / Kdim, k = idx - g * Kdim;
                int ij = g >> 4, enc = g & 15;
                g_W2[idx] = slz[ij * Kdim + k] + slpe[(enc >> 2) * Kdim + k]
                          + slpn[((enc >> 1) & 1) * Kdim + k]
                          + slpc[(enc & 1) * Kdim + k];
            }
        }
        // release: publish this prep block's writes, bump counter
        __syncthreads();
        __threadfence();
        if (t == 0) atomicAdd(&g_prepcnt, 1u);
        return;
    }

    if (blk < NPREP + NY) {
        // ================= Y STREAM ROLE (no gate) =================
        __shared__ float sY[TMEGA];
        int yb    = blk - NPREP;
        int ij    = yb / NYB;
        int chunk = yb - ij * NYB;
        int d0 = chunk * DCHUNK;
        int dl = t / 24, vq = t - dl * 24;     // 20 d's x 24 float4
        int d  = d0 + dl;
        float s = 0.f;
        if (d < Ddim) {
            const float4* q = (const float4*)Yv
                + (size_t)ij * (16 * Ddim * 24) + (size_t)d * 24 + vq;
#pragma unroll
            for (int enc = 0; enc < 16; ++enc) {
                float4 x = q[(size_t)enc * (Ddim * 24)];
                s += (x.x + x.y) + (x.z + x.w);
            }
        }
        sY[t] = s;
        __syncthreads();
        if (t < DCHUNK && d0 + t < Ddim) {
            float r = 0.f;
#pragma unroll
            for (int v = 0; v < 24; ++v) r += sY[t * 24 + v];
            g_ytr[ij * Ddim + d0 + t] = r;
        }
        return;
    }

    // ================= YPHI STREAM ROLE (gated on prep) =================
    __shared__ float  sW[Kdim];
    __shared__ float  swb[BPB * 16];           // [b][warp], 15 warps pad 16
    __shared__ double sred[NWARP];

    // acquire gate: wait until all 10 prep blocks have published
    if (t == 0) {
        while (atomicAdd(&g_prepcnt, 0u) < NPREP) __nanosleep(64);
        __threadfence();
    }
    __syncthreads();

    int pblk   = blk - NPREP - NY;             // 0..575
    int group  = pblk / SPLITS;                // ij*16 + enc
    int bsplit = pblk - group * SPLITS;
    int ij = group >> 4;

    if (t < Kdim) sW[t] = g_W2[group * Kdim + t];
    __syncthreads();

    // per-thread weights: one load, four smem adds — no MUFU
    float4 wv = *(const float4*)(g_L1 + ij * VK + 4 * t);
    int kb = (4 * t) % Kdim;                   // 4|20: never wraps inside a float4
    wv.x += sW[kb]; wv.y += sW[kb + 1]; wv.z += sW[kb + 2]; wv.w += sW[kb + 3];

    const float4* p = (const float4*)(yphi + (size_t)group * (Bdim * VK)
                                           + (size_t)bsplit * BPB * VK) + t;
    float acc = 0.f;
#pragma unroll 8
    for (int b = 0; b < BPB; ++b) {
        float4 x = p[(size_t)b * (VK / 4)];
        acc += x.x * wv.x; acc += x.y * wv.y;
        acc += x.z * wv.z; acc += x.w * wv.w;
        float s = (x.x + x.y) + (x.z + x.w);
#pragma unroll
        for (int off = 16; off; off >>= 1) s += __shfl_down_sync(0xffffffffu, s, off);
        if (lane == 0) swb[b * 16 + w] = s;
    }
    __syncthreads();
    if (t < BPB) {
        float s = 0.f;
#pragma unroll
        for (int w2 = 0; w2 < NWARP; ++w2) s += swb[t * 16 + w2];
        atomicAdd(&g_Wb[ij * Bdim + bsplit * BPB + t], s);
    }
#pragma unroll
    for (int off = 16; off; off >>= 1) acc += __shfl_down_sync(0xffffffffu, acc, off);
    if (lane == 0) sred[w] = (double)acc;
    __syncthreads();
    if (t == 0) {
        double s = 0.0;
#pragma unroll
        for (int w2 = 0; w2 < NWARP; ++w2) s += sred[w2];
        atomicAdd(&g_loss, s);
    }
}

// ---------------------------------------------------------------------------
// Finisher — Wb loads early, lmr logs + dot + scale; resets prep counter.
// ---------------------------------------------------------------------------
__global__ __launch_bounds__(256) void k_finish(
    const int* __restrict__ index, float* __restrict__ out)
{
    __shared__ double sred[256];
    int t = threadIdx.x;
    float wb[9];
#pragma unroll
    for (int ij = 0; ij < 9; ++ij) wb[ij] = g_Wb[ij * Bdim + t];
    int d = index[t];
    float y[9];
#pragma unroll
    for (int ij = 0; ij < 9; ++ij) y[ij] = g_ytr[ij * Ddim + d];
    float tot = ((y[0] + y[1]) + (y[2] + y[3]))
              + ((y[4] + y[5]) + (y[6] + y[7])) + y[8];
    float inv = 1.f / tot;
    float lmr[4];
    lmr[0] = __logf((y[0] + y[1] + y[3] + y[4]) * inv);  // m00
    lmr[1] = __logf((y[2] + y[5]) * inv);                // m01
    lmr[2] = __logf((y[6] + y[7]) * inv);                // m10
    lmr[3] = __logf(y[8] * inv);                         // m11
    double acc = 0.0;
#pragma unroll
    for (int ij = 0; ij < 9; ++ij) {
        int i = ij / 3, j = ij % 3;
        int sel = ((i == 2) ? 2 : 0) + ((j == 2) ? 1 : 0);
        acc += (double)wb[ij] * (double)lmr[sel];
    }
    sred[t] = acc;
    __syncthreads();
    for (int off = 128; off; off >>= 1) {
        if (t < off) sred[t] += sred[t + off];
        __syncthreads();
    }
    if (t == 0) {
        out[0] = (float)(-(g_loss + sred[0]) / (double)VK);
        g_prepcnt = 0u;                        // reset for next graph replay
    }
}

// ---------------------------------------------------------------------------
extern "C" void kernel_launch(void* const* d_in, const int* in_sizes, int n_in,
                              void* d_out, int out_size) {
    (void)in_sizes; (void)n_in; (void)out_size;
    const float* yphi = (const float*)d_in[0];
    const float* Yv   = (const float*)d_in[1];
    const float* T0p  = (const float*)d_in[2];
    const float* tp   = (const float*)d_in[3];
    const float* rp   = (const float*)d_in[4];
    const float* ep   = (const float*)d_in[5];
    const float* enp  = (const float*)d_in[6];
    const float* ecp  = (const float*)d_in[7];
    const int*   idx  = (const int*)d_in[8];
    float* out = (float*)d_out;

    k_mega<<<NBLK, TMEGA>>>(yphi, Yv, T0p, tp, rp, ep, enp, ecp);
    k_finish<<<1, 256>>>(idx, out);
}

// round 12
// speedup vs baseline: 1.0700x; 1.0700x over previous
#include <cuda_runtime.h>

#define Vdim   96
#define Kdim   20
#define Bdim   256
#define Ddim   1024
#define NIJ    9
#define GROUPS 144      // 3*3*4*2*2
#define VK     1920     // Vdim*Kdim

// kernel 1 geometry: 10 prep blocks + 468 Y blocks (independent, concurrent)
#define DCHUNK 20                  // d's per Y block
#define NYB    52                  // ceil(1024/20)
#define NY     (NIJ * NYB)         // 468
#define NPREP  10
#define NBLK1  (NPREP + NY)        // 478
// kernel 2 geometry: proven fine-grained yphi config
#define BPB    64                  // b's per yphi block
#define SPLITS (Bdim / BPB)        // 4
#define NPHI   (GROUPS * SPLITS)   // 576
#define TMEGA  480
#define NWARP  (TMEGA / 32)        // 15

// ---- scratch (static device globals — no runtime allocation) ----
__device__ float        g_ytr[NIJ * Ddim];    // sum over (e,n,c,v) of Y -> [ij][d]
__device__ float        g_L1[NIJ * VK];       // _T0 + log wt_i + log wr_j per (ij,v,k)
__device__ float        g_W2[GROUPS * Kdim];  // lq - logZ + L3 per (group,k)
__device__ float        g_lmr[4 * Bdim];      // log missing-rate per (sel,b)
__device__ double       g_loss;
__device__ unsigned int g_cntY;               // Y-block completion counter (k1)
__device__ unsigned int g_cnt2;               // yphi-block completion counter (k2)

// ---------------------------------------------------------------------------
// Kernel 1: prep (10 blocks) CONCURRENT with Y reduction (468 blocks).
// Last Y block computes g_lmr. No gates between roles (fully independent).
// ---------------------------------------------------------------------------
__global__ __launch_bounds__(TMEGA) void k_prepY(
    const float* __restrict__ Yv,  const float* __restrict__ T0p,
    const float* __restrict__ tp,  const float* __restrict__ rp,
    const float* __restrict__ ep,  const float* __restrict__ enp,
    const float* __restrict__ ecp, const int* __restrict__ index)
{
    int blk = blockIdx.x, t = threadIdx.x;
    int lane = t & 31, w = t >> 5;

    if (blk < NPREP) {
        // ================= PREP ROLE =================
        if (blk > 0) {
            // L1 slab for ij = blk-1: _T0 + log wt_i + log wr_j
            int ij = blk - 1;
            int i = ij / 3, j = ij % 3;
            for (int idx = t; idx < VK; idx += TMEGA) {
                float t0 = T0p[idx];
                float lwt = 0.f, lwr = 0.f;
                if (i < 2) {
                    float s = 1.f / (1.f + __expf(-tp[idx]));
                    lwt = __logf((i == 0) ? s : 1.f - s);
                }
                if (j < 2) {
                    float s = 1.f / (1.f + __expf(-rp[idx]));
                    lwr = __logf((j == 0) ? s : 1.f - s);
                }
                g_L1[ij * VK + idx] = t0 + lwt + lwr;
            }
        } else {
            // block 0: reductions + W2 + zero loss
            __shared__ float se[VK], st[VK], sr[VK];
            __shared__ float sprm[8 * Kdim];      // ep(4)|enp(2)|ecp(2)
            __shared__ float scolsum[Kdim];
            __shared__ float sZraw[NIJ * Kdim];
            __shared__ float slz[NIJ * Kdim];
            __shared__ float slpe[4 * Kdim], slpn[2 * Kdim], slpc[2 * Kdim];

            if (t < 8 * Kdim)
                sprm[t] = (t < 4 * Kdim) ? ep[t]
                        : (t < 6 * Kdim) ? enp[t - 4 * Kdim]
                                         : ecp[t - 6 * Kdim];
            for (int i = t; i < VK; i += TMEGA) {
                se[i] = __expf(T0p[i]);
                st[i] = 1.f / (1.f + __expf(-tp[i]));
                sr[i] = 1.f / (1.f + __expf(-rp[i]));
            }
            if (t == 0) g_loss = 0.0;
            __syncthreads();

            for (int o = w; o < Kdim; o += NWARP) {
                float s = 0.f;
                for (int v = lane; v < Vdim; v += 32) s += se[v * Kdim + o];
#pragma unroll
                for (int off = 16; off; off >>= 1)
                    s += __shfl_down_sync(0xffffffffu, s, off);
                if (lane == 0) scolsum[o] = s;
            }
            for (int o = w; o < NIJ * Kdim; o += NWARP) {
                int ij = o / Kdim, k = o - ij * Kdim, i = ij / 3, j = ij % 3;
                float s = 0.f;
                for (int v = lane; v < Vdim; v += 32) {
                    int r = v * Kdim + k;
                    float wt = (i == 0) ? st[r] : (i == 1) ? 1.f - st[r] : 1.f;
                    float wr = (j == 0) ? sr[r] : (j == 1) ? 1.f - sr[r] : 1.f;
                    s += se[r] * wt * wr;
                }
#pragma unroll
                for (int off = 16; off; off >>= 1)
                    s += __shfl_down_sync(0xffffffffu, s, off);
                if (lane == 0) sZraw[o] = s;
            }
            __syncthreads();

            if (t < Kdim) {
                float s, l;
                s = 0.f; for (int e = 0; e < 4; ++e) s += __expf(sprm[e * Kdim + t]);
                l = __logf(s);
                for (int e = 0; e < 4; ++e) slpe[e * Kdim + t] = sprm[e * Kdim + t] - l;
                s = 0.f; for (int n = 0; n < 2; ++n) s += __expf(sprm[(4 + n) * Kdim + t]);
                l = __logf(s);
                for (int n = 0; n < 2; ++n) slpn[n * Kdim + t] = sprm[(4 + n) * Kdim + t] - l;
                s = 0.f; for (int c = 0; c < 2; ++c) s += __expf(sprm[(6 + c) * Kdim + t]);
                l = __logf(s);
                for (int c = 0; c < 2; ++c) slpc[c * Kdim + t] = sprm[(6 + c) * Kdim + t] - l;
            }
            if (t < NIJ * Kdim) {
                int ij = t / Kdim, k = t - ij * Kdim;
                int i = ij / 3, j = ij % 3;
                float inv = 1.f / scolsum[k];
                float pt = sZraw[2 * Kdim + k] * inv;   // ij=(0,2)
                float pr = sZraw[6 * Kdim + k] * inv;   // ij=(2,0)
                float lqt = (i == 0) ? __logf(pt) : (i == 1) ? __logf(1.f - pt) : 0.f;
                float lqr = (j == 0) ? __logf(pr) : (j == 1) ? __logf(1.f - pr) : 0.f;
                slz[t] = lqt + lqr - __logf(sZraw[t]);
            }
            __syncthreads();

            for (int idx = t; idx < GROUPS * Kdim; idx += TMEGA) {
                int g = idx / Kdim, k = idx - g * Kdim;
                int ij = g >> 4, enc = g & 15;
                g_W2[idx] = slz[ij * Kdim + k] + slpe[(enc >> 2) * Kdim + k]
                          + slpn[((enc >> 1) & 1) * Kdim + k]
                          + slpc[(enc & 1) * Kdim + k];
            }
        }
        return;   // prep blocks: no fence needed — kernel boundary publishes
    }

    // ================= Y STREAM ROLE =================
    {
        __shared__ float sY[TMEGA];
        __shared__ int   sLast;
        int yb    = blk - NPREP;
        int ij    = yb / NYB;
        int chunk = yb - ij * NYB;
        int d0 = chunk * DCHUNK;
        int dl = t / 24, vq = t - dl * 24;     // 20 d's x 24 float4
        int d  = d0 + dl;
        float s = 0.f;
        if (d < Ddim) {
            const float4* q = (const float4*)Yv
                + (size_t)ij * (16 * Ddim * 24) + (size_t)d * 24 + vq;
#pragma unroll
            for (int enc = 0; enc < 16; ++enc) {
                float4 x = q[(size_t)enc * (Ddim * 24)];
                s += (x.x + x.y) + (x.z + x.w);
            }
        }
        sY[t] = s;
        __syncthreads();
        if (t < DCHUNK && d0 + t < Ddim) {
            float r = 0.f;
#pragma unroll
            for (int v = 0; v < 24; ++v) r += sY[t * 24 + v];
            g_ytr[ij * Ddim + d0 + t] = r;
            __threadfence();                   // writer-thread release (1 warp)
        }
        __syncthreads();
        if (t == 0) {
            unsigned int v = atomicAdd(&g_cntY, 1u);
            sLast = (v == NY - 1) ? 1 : 0;
        }
        __syncthreads();
        if (!sLast) return;

        // last Y block: compute log missing-rates (overlaps residual prep work)
        if (t == 0) __threadfence();           // acquire
        __syncthreads();
        if (t < Bdim) {
            int dd = index[t];
            float y[9];
#pragma unroll
            for (int ij2 = 0; ij2 < 9; ++ij2) y[ij2] = g_ytr[ij2 * Ddim + dd];
            float tot = ((y[0] + y[1]) + (y[2] + y[3]))
                      + ((y[4] + y[5]) + (y[6] + y[7])) + y[8];
            float inv = 1.f / tot;
            g_lmr[t]            = __logf((y[0] + y[1] + y[3] + y[4]) * inv);  // m00
            g_lmr[Bdim + t]     = __logf((y[2] + y[5]) * inv);                // m01
            g_lmr[2 * Bdim + t] = __logf((y[6] + y[7]) * inv);                // m10
            g_lmr[3 * Bdim + t] = __logf(y[8] * inv);                         // m11
        }
        if (t == 0) g_cntY = 0u;               // reset for next graph replay
    }
}

// ---------------------------------------------------------------------------
// Kernel 2: yphi stream (576 blocks). Weights fold L1 + W2 + lmr — no Wb
// machinery, no shuffles in the inner loop. Last block writes the output.
// ---------------------------------------------------------------------------
__global__ __launch_bounds__(TMEGA) void k_yphi(
    const float* __restrict__ yphi, float* __restrict__ out)
{
    __shared__ float  sW[Kdim];
    __shared__ float  slmr[BPB];
    __shared__ double sred[NWARP];
    __shared__ int    sLast;

    int blk = blockIdx.x, t = threadIdx.x;
    int lane = t & 31, w = t >> 5;

    int group  = blk / SPLITS;                 // ij*16 + enc
    int bsplit = blk - group * SPLITS;
    int ij = group >> 4;
    int i = ij / 3, j = ij % 3;
    int sel = ((i == 2) ? 2 : 0) + ((j == 2) ? 1 : 0);

    if (t < Kdim) sW[t]  = g_W2[group * Kdim + t];
    if (t < BPB)  slmr[t] = g_lmr[sel * Bdim + bsplit * BPB + t];
    __syncthreads();

    // per-thread weights: one load, four smem adds — no MUFU
    float4 wv = *(const float4*)(g_L1 + ij * VK + 4 * t);
    int kb = (4 * t) % Kdim;                   // 4|20: never wraps inside a float4
    wv.x += sW[kb]; wv.y += sW[kb + 1]; wv.z += sW[kb + 2]; wv.w += sW[kb + 3];

    const float4* p = (const float4*)(yphi + (size_t)group * (Bdim * VK)
                                           + (size_t)bsplit * BPB * VK) + t;
    float acc = 0.f, acc2 = 0.f;
#pragma unroll 8
    for (int b = 0; b < BPB; ++b) {
        float4 x = p[(size_t)b * (VK / 4)];
        acc  += x.x * wv.x; acc += x.y * wv.y;
        acc  += x.z * wv.z; acc += x.w * wv.w;
        acc2 += ((x.x + x.y) + (x.z + x.w)) * slmr[b];
    }
    float v = acc + acc2;
#pragma unroll
    for (int off = 16; off; off >>= 1) v += __shfl_down_sync(0xffffffffu, v, off);
    if (lane == 0) sred[w] = (double)v;
    __syncthreads();
    if (t == 0) {
        double s = 0.0;
#pragma unroll
        for (int w2 = 0; w2 < NWARP; ++w2) s += sred[w2];
        atomicAdd(&g_loss, s);
        __threadfence();                       // order loss-add before counter
        unsigned int c = atomicAdd(&g_cnt2, 1u);
        sLast = (c == NPHI - 1) ? 1 : 0;
    }
    __syncthreads();
    if (!sLast) return;

    if (t == 0) {
        __threadfence();                       // acquire
        double L = atomicAdd(&g_loss, 0.0);    // atomic read (L2-coherent)
        out[0] = (float)(-L / (double)VK);
        g_cnt2 = 0u;                           // reset for next graph replay
    }
}

// ---------------------------------------------------------------------------
extern "C" void kernel_launch(void* const* d_in, const int* in_sizes, int n_in,
                              void* d_out, int out_size) {
    (void)in_sizes; (void)n_in; (void)out_size;
    const float* yphi = (const float*)d_in[0];
    const float* Yv   = (const float*)d_in[1];
    const float* T0p  = (const float*)d_in[2];
    const float* tp   = (const float*)d_in[3];
    const float* rp   = (const float*)d_in[4];
    const float* ep   = (const float*)d_in[5];
    const float* enp  = (const float*)d_in[6];
    const float* ecp  = (const float*)d_in[7];
    const int*   idx  = (const int*)d_in[8];
    float* out = (float*)d_out;

    k_prepY<<<NBLK1, TMEGA>>>(Yv, T0p, tp, rp, ep, enp, ecp, idx);
    k_yphi<<<NPHI, TMEGA>>>(yphi, out);
}